// round 15
// baseline (speedup 1.0000x reference)
#include <cuda_runtime.h>
#include <math.h>

#define NT    4096
#define SEQ   128
#define DIN   32
#define DLAT  64
#define NU    256
#define INDIM 160
#define TM    32
#define NTH   256
#define HS    36    // h1 column stride (floats): 16B-aligned, bank-spread

typedef unsigned long long u64;
typedef ulonglong2 u64x2;

// ---------- packed f32x2 helpers ----------
__device__ __forceinline__ u64 bcast2(float a) {
    u64 r; asm("mov.b64 %0, {%1, %1};" : "=l"(r) : "f"(a)); return r;
}
__device__ __forceinline__ u64 pk2(float x, float y) {
    u64 r; asm("mov.b64 %0, {%1, %2};" : "=l"(r) : "f"(x), "f"(y)); return r;
}
__device__ __forceinline__ float2 unpk(u64 v) {
    float2 f; asm("mov.b64 {%0, %1}, %2;" : "=f"(f.x), "=f"(f.y) : "l"(v)); return f;
}
__device__ __forceinline__ void fma2(u64& d, u64 a, u64 b) {
    asm("fma.rn.f32x2 %0, %1, %2, %0;" : "+l"(d) : "l"(a), "l"(b));
}
__device__ __forceinline__ u64 mul2(u64 a, u64 b) {
    u64 d; asm("mul.rn.f32x2 %0, %1, %2;" : "=l"(d) : "l"(a), "l"(b)); return d;
}
__device__ __forceinline__ float tanh_f(float x) {
    return 1.0f - __fdividef(2.0f, __expf(2.0f * x) + 1.0f);
}
__device__ __forceinline__ float sigmoid_f(float x) {
    return __fdividef(1.0f, 1.0f + __expf(-x));
}

// ---------- cp.async helpers ----------
__device__ __forceinline__ void cpa16(unsigned d, const float* s) {
    asm volatile("cp.async.cg.shared.global [%0], [%1], 16;" :: "r"(d), "l"(s));
}
#define CPCOMMIT() asm volatile("cp.async.commit_group;")
#define CPWAIT1()  asm volatile("cp.async.wait_group 1;")
#define CPWAIT0()  asm volatile("cp.async.wait_group 0;")

// 16KB slab, one source (256 threads x 64B)
__device__ __forceinline__ void copy16(float* dst, const float* __restrict__ src, int tid) {
    unsigned d = (unsigned)__cvta_generic_to_shared(dst) + tid * 16;
#pragma unroll
    for (int i = 0; i < 4; ++i) cpa16(d + i * 4096, src + tid * 4 + i * 1024);
}
// 8KB + 8KB, two sources
__device__ __forceinline__ void copy8x2(float* dst, const float* __restrict__ sa,
                                        const float* __restrict__ sb, int tid) {
    unsigned d = (unsigned)__cvta_generic_to_shared(dst) + tid * 16;
#pragma unroll
    for (int i = 0; i < 2; ++i) cpa16(d + i * 4096, sa + tid * 4 + i * 1024);
#pragma unroll
    for (int i = 0; i < 2; ++i) cpa16(d + 8192 + i * 4096, sb + tid * 4 + i * 1024);
}

__device__ __forceinline__ int nxt1(int c) { return (c == 2) ? 0 : c + 1; }
__device__ __forceinline__ int nxt2(int c) { return (c == 0) ? 2 : c - 1; }

// ---------- smem layouts ----------
#define XI(c, p)  ((p)*128 + (((c)&1)*32 + ((c)>>1))*2)     // 64-col buffers
#define YI(c, p)  ((p)*320 + (((c)&1)*80 + ((c)>>1))*2)     // 160-col buffers
// h1: [slot sigma(c)][pair], sigma(c) = (c&3)*64 + (c>>2); addr = sigma*HS + pair*2

struct Smem {
    float wbuf[3][4096];   // 3 x 16KB weight slabs
    float yT [16 * 128];
    float lvT[16 * 128];
    float uT [16 * 128];
    float ycT[16 * 320];
    float ccT[16 * 320];
    float h1A[NU * HS];    // 36KB
    float h1B[NU * HS];
    float ts[SEQ];
};   // ~184.5 KB

// ---------- first-layer slab (R11 geometry): acc += A^T W over SK rows ----------
template<int COLS, int SK>
__device__ __forceinline__ void fl_slab(const float* __restrict__ AT,
                                        const float* __restrict__ Ws,
                                        int k0, u64 acc[4][4], int cg, int rg)
{
    const float4* W4 = reinterpret_cast<const float4*>(Ws) + cg;
    const float* Ap = AT + (4 * rg) * (2 * COLS);
#pragma unroll 4
    for (int kk = 0; kk < SK; ++kk) {
        const int k = k0 + kk;
        float4 w = W4[kk * 64];
        u64 w0 = bcast2(w.x), w1 = bcast2(w.y), w2 = bcast2(w.z), w3 = bcast2(w.w);
        const int m = ((k & 1) * (COLS / 2) + (k >> 1)) * 2;
#pragma unroll
        for (int q = 0; q < 4; ++q) {
            u64 a = *reinterpret_cast<const u64*>(Ap + q * (2 * COLS) + m);
            fma2(acc[q][0], a, w0); fma2(acc[q][1], a, w1);
            fma2(acc[q][2], a, w2); fma2(acc[q][3], a, w3);
        }
    }
}

template<int COLS, int SK>
__device__ __forceinline__ void fl_slab_dual(const float* __restrict__ AT,
                                             const float* __restrict__ Wsu,
                                             const float* __restrict__ Wsr,
                                             int k0, u64 aU[4][4], u64 aR[4][4],
                                             int cg, int rg)
{
    const float4* WU = reinterpret_cast<const float4*>(Wsu) + cg;
    const float4* WR = reinterpret_cast<const float4*>(Wsr) + cg;
    const float* Ap = AT + (4 * rg) * (2 * COLS);
#pragma unroll 4
    for (int kk = 0; kk < SK; ++kk) {
        const int k = k0 + kk;
        float4 wu = WU[kk * 64];
        float4 wr = WR[kk * 64];
        u64 u0 = bcast2(wu.x), u1 = bcast2(wu.y), u2 = bcast2(wu.z), u3 = bcast2(wu.w);
        u64 r0 = bcast2(wr.x), r1 = bcast2(wr.y), r2 = bcast2(wr.z), r3 = bcast2(wr.w);
        const int m = ((k & 1) * (COLS / 2) + (k >> 1)) * 2;
#pragma unroll
        for (int q = 0; q < 4; ++q) {
            u64 a = *reinterpret_cast<const u64*>(Ap + q * (2 * COLS) + m);
            fma2(aU[q][0], a, u0); fma2(aU[q][1], a, u1);
            fma2(aU[q][2], a, u2); fma2(aU[q][3], a, u3);
            fma2(aR[q][0], a, r0); fma2(aR[q][1], a, r1);
            fma2(aR[q][2], a, r2); fma2(aR[q][3], a, r3);
        }
    }
}

// first-layer epilogue: tanh + store into h1 [slot][pair]
__device__ __forceinline__ void fl_epi(u64 acc[4][4], const float* __restrict__ bias,
                                       float* __restrict__ OT, int cg, int rg)
{
    float4 b4 = reinterpret_cast<const float4*>(bias)[cg];
    float bb[4] = {b4.x, b4.y, b4.z, b4.w};
#pragma unroll
    for (int q = 0; q < 4; ++q)
#pragma unroll
        for (int j = 0; j < 4; ++j) {
            float2 v = unpk(acc[q][j]);
            v.x = tanh_f(v.x + bb[j]);
            v.y = tanh_f(v.y + bb[j]);
            // col 4cg+j -> slot j*64+cg ; pair 4rg+q
            *reinterpret_cast<u64*>(OT + (j * 64 + cg) * HS + (4 * rg + q) * 2) = pk2(v.x, v.y);
        }
}

// ---------- second layer (N=64): thread = (col c, pair-quad g) ----------
// A reads: two broadcast LDS.128 covering pairs 4g..4g+3; W: scalar LDS.32 (1 wf/warp)
template<int SR>
__device__ __forceinline__ void sl2(const float* __restrict__ Ah,
                                    const float* __restrict__ Ws,
                                    int k0, int c, int g, u64 acc[4])
{
    const float* Ab = Ah + (k0 >> 2) * HS + 8 * g;
    const float* Wp = Ws + c;
#pragma unroll 2
    for (int t = 0; t < SR / 4; ++t) {
#pragma unroll
        for (int j = 0; j < 4; ++j) {
            const float* ap = Ab + (j * 64 + t) * HS;
            u64x2 a01 = *reinterpret_cast<const u64x2*>(ap);
            u64x2 a23 = *reinterpret_cast<const u64x2*>(ap + 4);
            u64 w = bcast2(Wp[(4 * t + j) * 64]);
            fma2(acc[0], a01.x, w); fma2(acc[1], a01.y, w);
            fma2(acc[2], a23.x, w); fma2(acc[3], a23.y, w);
        }
    }
}

template<int SR>
__device__ __forceinline__ void sl2_dual(const float* __restrict__ Au,
                                         const float* __restrict__ Ar,
                                         const float* __restrict__ Wsu,
                                         const float* __restrict__ Wsr,
                                         int k0, int c, int g,
                                         u64 aU[4], u64 aR[4])
{
    const int boff = (k0 >> 2) * HS + 8 * g;
    const float* AuB = Au + boff;
    const float* ArB = Ar + boff;
    const float* WuP = Wsu + c;
    const float* WrP = Wsr + c;
#pragma unroll 2
    for (int t = 0; t < SR / 4; ++t) {
#pragma unroll
        for (int j = 0; j < 4; ++j) {
            const int o = (j * 64 + t) * HS;
            u64x2 ua = *reinterpret_cast<const u64x2*>(AuB + o);
            u64x2 ub = *reinterpret_cast<const u64x2*>(AuB + o + 4);
            u64x2 ra = *reinterpret_cast<const u64x2*>(ArB + o);
            u64x2 rb = *reinterpret_cast<const u64x2*>(ArB + o + 4);
            u64 wu = bcast2(WuP[(4 * t + j) * 64]);
            u64 wr = bcast2(WrP[(4 * t + j) * 64]);
            fma2(aU[0], ua.x, wu); fma2(aU[1], ua.y, wu);
            fma2(aU[2], ub.x, wu); fma2(aU[3], ub.y, wu);
            fma2(aR[0], ra.x, wr); fma2(aR[1], ra.y, wr);
            fma2(aR[2], rb.x, wr); fma2(aR[3], rb.y, wr);
        }
    }
}

// candidate layer 2 (N=128): thread handles cols c and c+64
template<int SR>
__device__ __forceinline__ void f2(const float* __restrict__ Ah,
                                   const float* __restrict__ Ws,
                                   int k0, int c, int g, u64 aS[4], u64 aD[4])
{
    const float* Ab = Ah + (k0 >> 2) * HS + 8 * g;
    const float* WpL = Ws + c;
    const float* WpH = Ws + 64 + c;
#pragma unroll 2
    for (int t = 0; t < SR / 4; ++t) {
#pragma unroll
        for (int j = 0; j < 4; ++j) {
            const float* ap = Ab + (j * 64 + t) * HS;
            u64x2 a01 = *reinterpret_cast<const u64x2*>(ap);
            u64x2 a23 = *reinterpret_cast<const u64x2*>(ap + 4);
            u64 wl = bcast2(WpL[(4 * t + j) * 128]);
            u64 wh = bcast2(WpH[(4 * t + j) * 128]);
            fma2(aS[0], a01.x, wl); fma2(aS[1], a01.y, wl);
            fma2(aS[2], a23.x, wl); fma2(aS[3], a23.y, wl);
            fma2(aD[0], a01.x, wh); fma2(aD[1], a01.y, wh);
            fma2(aD[2], a23.x, wh); fma2(aD[3], a23.y, wh);
        }
    }
}

__global__ __launch_bounds__(NTH, 1)
void ode_rnn_kernel(const float* __restrict__ data,
                    const float* __restrict__ tsteps,
                    const float* __restrict__ Wo1, const float* __restrict__ bo1,
                    const float* __restrict__ Wo2, const float* __restrict__ bo2,
                    const float* __restrict__ Wu1, const float* __restrict__ bu1,
                    const float* __restrict__ Wu2, const float* __restrict__ bu2,
                    const float* __restrict__ Wr1, const float* __restrict__ br1,
                    const float* __restrict__ Wr2, const float* __restrict__ br2,
                    const float* __restrict__ Wn1, const float* __restrict__ bn1,
                    const float* __restrict__ Wn2, const float* __restrict__ bn2,
                    float* __restrict__ out)
{
    extern __shared__ float smem_raw[];
    Smem* S = reinterpret_cast<Smem*>(smem_raw);
    const int tid = threadIdx.x;
    const int traj0 = blockIdx.x * TM;

    const int cg = tid & 63;          // first-layer cols 4cg..4cg+3
    const int rg = tid >> 6;          // first-layer pair quad 0..3
    const int c  = tid & 63;          // second-layer single column
    const int g  = tid >> 6;          // second-layer pair quad (pairs 4g..4g+3)

    for (int i = tid; i < 16 * 128; i += NTH) { S->yT[i] = 0.f; S->lvT[i] = 0.f; }
    for (int i = tid; i < SEQ; i += NTH) S->ts[i] = tsteps[i];

    // prologue: first two slabs of Wo1
    copy16(S->wbuf[0], Wo1, tid);        CPCOMMIT();
    copy16(S->wbuf[1], Wo1 + 4096, tid); CPCOMMIT();
    int cb = 0;
    __syncthreads();

    for (int s = 0; s < SEQ - 1; ++s) {
        const float dt = (s == 0) ? (S->ts[1] - S->ts[0]) : (S->ts[s] - S->ts[s + 1]);

        // x prefetch (global); lv -> ycT[64:128) (same-thread RAW vs prev F epilogue)
        float xv[4];
#pragma unroll
        for (int e = 0; e < 4; ++e) {
            int idx = tid + e * NTH;
            int r = idx >> 5, cc_ = idx & 31;
            xv[e] = data[(size_t)(traj0 + r) * SEQ * DIN + (size_t)(s + 1) * DIN + cc_];
        }
#pragma unroll
        for (int p = 0; p < 4; ++p) {
            int pr = 4 * g + p;
            u64 v = *reinterpret_cast<const u64*>(S->lvT + XI(c, pr));
            *reinterpret_cast<u64*>(S->ycT + YI(c + DLAT, pr)) = v;
        }

        // ===== Phase A: ODE L1 (4 slabs x 16 k-rows) =====
        u64 aA[4][4];
#pragma unroll
        for (int q = 0; q < 4; ++q) { aA[q][0]=0; aA[q][1]=0; aA[q][2]=0; aA[q][3]=0; }
#pragma unroll 1
        for (int i = 0; i < 4; ++i) {
            CPWAIT1(); __syncthreads();
            if (i < 2) copy16(S->wbuf[nxt2(cb)], Wo1 + (i + 2) * 4096, tid);
            else       copy16(S->wbuf[nxt2(cb)], Wo2 + (i - 2) * 4096, tid);
            CPCOMMIT();
            fl_slab<DLAT, 16>(S->yT, S->wbuf[cb], 16 * i, aA, cg, rg);
            if (i == 3) {
                fl_epi(aA, bo1, S->h1A, cg, rg);
#pragma unroll
                for (int e = 0; e < 4; ++e) {     // stage x -> ycT/ccT[128:160)
                    int idx = tid + e * NTH;
                    int r = idx >> 5, cc_ = idx & 31;
                    int a = YI(2 * DLAT + cc_, r >> 1) + (r & 1);
                    S->ycT[a] = xv[e];
                    S->ccT[a] = xv[e];
                }
            }
            cb = nxt1(cb);
        }

        // ===== Phase B: ODE L2 (4 slabs x 64 k-rows) =====
        u64 aB[4] = {0, 0, 0, 0};
#pragma unroll 1
        for (int i = 0; i < 4; ++i) {
            CPWAIT1(); __syncthreads();
            if (i < 2) copy16(S->wbuf[nxt2(cb)], Wo2 + (i + 2) * 4096, tid);
            else       copy8x2(S->wbuf[nxt2(cb)], Wu1 + (i - 2) * 2048, Wr1 + (i - 2) * 2048, tid);
            CPCOMMIT();
            sl2<64>(S->h1A, S->wbuf[cb], 64 * i, c, g, aB);
            if (i == 3) {   // epilogue: ycT[0:64) = y + (o+b)*dt
                float b = bo2[c];
#pragma unroll
                for (int p = 0; p < 4; ++p) {
                    int pr = 4 * g + p;
                    float2 o = unpk(aB[p]);
                    float2 y = unpk(*reinterpret_cast<const u64*>(S->yT + XI(c, pr)));
                    float rx = fmaf(o.x + b, dt, y.x);
                    float ry = fmaf(o.y + b, dt, y.y);
                    *reinterpret_cast<u64*>(S->ycT + YI(c, pr)) = pk2(rx, ry);
                }
            }
            cb = nxt1(cb);
        }

        // ===== Phase C: update+reset L1 (20 dual slabs x 8 k-rows) =====
        u64 aU4[4][4], aR4[4][4];
#pragma unroll
        for (int q = 0; q < 4; ++q)
#pragma unroll
            for (int j = 0; j < 4; ++j) { aU4[q][j] = 0; aR4[q][j] = 0; }
#pragma unroll 1
        for (int ci = 0; ci < 20; ++ci) {
            CPWAIT1(); __syncthreads();
            if (ci < 18) copy8x2(S->wbuf[nxt2(cb)], Wu1 + (ci + 2) * 2048, Wr1 + (ci + 2) * 2048, tid);
            else         copy8x2(S->wbuf[nxt2(cb)], Wu2 + (ci - 18) * 2048, Wr2 + (ci - 18) * 2048, tid);
            CPCOMMIT();
            fl_slab_dual<INDIM, 8>(S->ycT, S->wbuf[cb], S->wbuf[cb] + 2048, 8 * ci, aU4, aR4, cg, rg);
            if (ci == 19) {
                fl_epi(aU4, bu1, S->h1A, cg, rg);
                fl_epi(aR4, br1, S->h1B, cg, rg);
            }
            cb = nxt1(cb);
        }

        // ===== Phase D: update+reset L2 (8 dual slabs x 32 k-rows) =====
        u64 dU[4] = {0, 0, 0, 0}, dR[4] = {0, 0, 0, 0};
#pragma unroll 1
        for (int di = 0; di < 8; ++di) {
            CPWAIT1(); __syncthreads();
            if (di < 6) copy8x2(S->wbuf[nxt2(cb)], Wu2 + (di + 2) * 2048, Wr2 + (di + 2) * 2048, tid);
            else        copy16(S->wbuf[nxt2(cb)], Wn1 + (di - 6) * 4096, tid);
            CPCOMMIT();
            sl2_dual<32>(S->h1A, S->h1B, S->wbuf[cb], S->wbuf[cb] + 2048, 32 * di, c, g, dU, dR);
            if (di == 7) {   // epilogue -> uT, ccT[0:128)
                float bu = bu2[c];
                float br = br2[c];
#pragma unroll
                for (int p = 0; p < 4; ++p) {
                    int pr = 4 * g + p;
                    float2 vu = unpk(dU[p]);
                    *reinterpret_cast<u64*>(S->uT + XI(c, pr)) =
                        pk2(sigmoid_f(vu.x + bu), sigmoid_f(vu.y + bu));
                    float2 vr = unpk(dR[p]);
                    u64 rpair = pk2(sigmoid_f(vr.x + br), sigmoid_f(vr.y + br));
                    u64 ylo = *reinterpret_cast<const u64*>(S->ycT + YI(c, pr));
                    u64 yhi = *reinterpret_cast<const u64*>(S->ycT + YI(c + DLAT, pr));
                    *reinterpret_cast<u64*>(S->ccT + YI(c, pr))        = mul2(ylo, rpair);
                    *reinterpret_cast<u64*>(S->ccT + YI(c + DLAT, pr)) = mul2(yhi, rpair);
                }
            }
            cb = nxt1(cb);
        }

        // ===== Phase E: candidate L1 (10 slabs x 16 k-rows) =====
        u64 aE[4][4];
#pragma unroll
        for (int q = 0; q < 4; ++q) { aE[q][0]=0; aE[q][1]=0; aE[q][2]=0; aE[q][3]=0; }
#pragma unroll 1
        for (int ei = 0; ei < 10; ++ei) {
            CPWAIT1(); __syncthreads();
            if (ei < 8) copy16(S->wbuf[nxt2(cb)], Wn1 + (ei + 2) * 4096, tid);
            else        copy16(S->wbuf[nxt2(cb)], Wn2 + (ei - 8) * 4096, tid);
            CPCOMMIT();
            fl_slab<INDIM, 16>(S->ccT, S->wbuf[cb], 16 * ei, aE, cg, rg);
            if (ei == 9) fl_epi(aE, bn1, S->h1A, cg, rg);
            cb = nxt1(cb);
        }

        // ===== Phase F: candidate L2 (8 slabs x 32 k-rows) + fused state update =====
        u64 fS[4] = {0, 0, 0, 0}, fD[4] = {0, 0, 0, 0};
#pragma unroll 1
        for (int fi = 0; fi < 8; ++fi) {
            CPWAIT1(); __syncthreads();
            if (fi < 6) copy16(S->wbuf[nxt2(cb)], Wn2 + (fi + 2) * 4096, tid);
            else        copy16(S->wbuf[nxt2(cb)], Wo1 + (fi - 6) * 4096, tid);  // next-step A
            CPCOMMIT();
            f2<32>(S->h1A, S->wbuf[cb], 32 * fi, c, g, fS, fD);
            if (fi == 7) {
                float bl = bn2[c];
                float bh = bn2[DLAT + c];
#pragma unroll
                for (int p = 0; p < 4; ++p) {
                    int pr = 4 * g + p;
                    float2 ns = unpk(fS[p]);
                    ns.x += bl; ns.y += bl;
                    float2 nd = unpk(fD[p]);
                    nd.x = fabsf(nd.x + bh); nd.y = fabsf(nd.y + bh);
                    float2 uu = unpk(*reinterpret_cast<const u64*>(S->uT + XI(c, pr)));
                    float2 yo = unpk(*reinterpret_cast<const u64*>(S->ycT + YI(c, pr)));
                    float2 lo = unpk(*reinterpret_cast<const u64*>(S->lvT + XI(c, pr)));
                    float ny0 = (1.f - uu.x) * ns.x + uu.x * yo.x;
                    float ny1 = (1.f - uu.y) * ns.y + uu.y * yo.y;
                    float nl0 = (1.f - uu.x) * nd.x + uu.x * lo.x;
                    float nl1 = (1.f - uu.y) * nd.y + uu.y * lo.y;
                    *reinterpret_cast<u64*>(S->yT + XI(c, pr))  = pk2(ny0, ny1);
                    *reinterpret_cast<u64*>(S->lvT + XI(c, pr)) = pk2(nl0, nl1);
                }
            }
            cb = nxt1(cb);
        }
    }

    CPWAIT0(); __syncthreads();

    // ===== output: yi (4096x64) then yi_logvar (4096x64) =====
    for (int i = tid; i < TM * DLAT; i += NTH) {
        int r = i >> 6, cc_ = i & 63;
        int a = XI(cc_, r >> 1) + (r & 1);
        out[(size_t)(traj0 + r) * DLAT + cc_] = S->yT[a];
        out[(size_t)NT * DLAT + (size_t)(traj0 + r) * DLAT + cc_] = S->lvT[a];
    }
}

extern "C" void kernel_launch(void* const* d_in, const int* in_sizes, int n_in,
                              void* d_out, int out_size) {
    const float* data = (const float*)d_in[0];
    const float* ts   = (const float*)d_in[1];
    const float* Wo1  = (const float*)d_in[2];
    const float* bo1  = (const float*)d_in[3];
    const float* Wo2  = (const float*)d_in[4];
    const float* bo2  = (const float*)d_in[5];
    const float* Wu1  = (const float*)d_in[6];
    const float* bu1  = (const float*)d_in[7];
    const float* Wu2  = (const float*)d_in[8];
    const float* bu2  = (const float*)d_in[9];
    const float* Wr1  = (const float*)d_in[10];
    const float* br1  = (const float*)d_in[11];
    const float* Wr2  = (const float*)d_in[12];
    const float* br2  = (const float*)d_in[13];
    const float* Wn1  = (const float*)d_in[14];
    const float* bn1  = (const float*)d_in[15];
    const float* Wn2  = (const float*)d_in[16];
    const float* bn2  = (const float*)d_in[17];
    float* out = (float*)d_out;

    const int smem = (int)sizeof(Smem);
    cudaFuncSetAttribute(ode_rnn_kernel,
                         cudaFuncAttributeMaxDynamicSharedMemorySize, smem);
    ode_rnn_kernel<<<NT / TM, NTH, smem>>>(
        data, ts, Wo1, bo1, Wo2, bo2, Wu1, bu1, Wu2, bu2,
        Wr1, br1, Wr2, br2, Wn1, bn1, Wn2, bn2, out);
}

// round 16
// speedup vs baseline: 1.1163x; 1.1163x over previous
#include <cuda_runtime.h>
#include <math.h>

#define NT    4096
#define SEQ   128
#define DIN   32
#define DLAT  64
#define NU    256
#define INDIM 160
#define TM    32
#define NTH   256

typedef unsigned long long u64;

// ---------- packed f32x2 helpers ----------
__device__ __forceinline__ u64 bcast2(float a) {
    u64 r; asm("mov.b64 %0, {%1, %1};" : "=l"(r) : "f"(a)); return r;
}
__device__ __forceinline__ u64 pk2(float x, float y) {
    u64 r; asm("mov.b64 %0, {%1, %2};" : "=l"(r) : "f"(x), "f"(y)); return r;
}
__device__ __forceinline__ float2 unpk(u64 v) {
    float2 f; asm("mov.b64 {%0, %1}, %2;" : "=f"(f.x), "=f"(f.y) : "l"(v)); return f;
}
__device__ __forceinline__ void fma2(u64& d, u64 a, u64 b) {
    asm("fma.rn.f32x2 %0, %1, %2, %0;" : "+l"(d) : "l"(a), "l"(b));
}
__device__ __forceinline__ u64 mul2(u64 a, u64 b) {
    u64 d; asm("mul.rn.f32x2 %0, %1, %2;" : "=l"(d) : "l"(a), "l"(b)); return d;
}
// fast activations on the MUFU pipe: __expf err ~2^-22, branchless, safe at +/-inf
__device__ __forceinline__ float tanh_f(float x) {
    return 1.0f - __fdividef(2.0f, __expf(2.0f * x) + 1.0f);
}
__device__ __forceinline__ float sigmoid_f(float x) {
    return __fdividef(1.0f, 1.0f + __expf(-x));
}

// ---------- cp.async helpers ----------
__device__ __forceinline__ void cpa16(unsigned d, const float* s) {
    asm volatile("cp.async.cg.shared.global [%0], [%1], 16;" :: "r"(d), "l"(s));
}
#define CPCOMMIT() asm volatile("cp.async.commit_group;")
#define CPWAIT1()  asm volatile("cp.async.wait_group 1;")
#define CPWAIT0()  asm volatile("cp.async.wait_group 0;")

// 32KB slab from one source
__device__ __forceinline__ void copy32(float* dst, const float* __restrict__ src, int tid) {
    unsigned d = (unsigned)__cvta_generic_to_shared(dst) + tid * 16;
    const float* s = src + tid * 4;
#pragma unroll
    for (int i = 0; i < 8; ++i) cpa16(d + i * 4096, s + i * 1024);
}
// 16KB + 16KB from two sources
__device__ __forceinline__ void copy16x2(float* dst, const float* __restrict__ sa,
                                         const float* __restrict__ sb, int tid) {
    unsigned d = (unsigned)__cvta_generic_to_shared(dst) + tid * 16;
#pragma unroll
    for (int i = 0; i < 4; ++i) cpa16(d + i * 4096, sa + tid * 4 + i * 1024);
#pragma unroll
    for (int i = 0; i < 4; ++i) cpa16(d + 16384 + i * 4096, sb + tid * 4 + i * 1024);
}

// buffer index cycling mod 3
__device__ __forceinline__ int nxt1(int c) { return (c == 2) ? 0 : c + 1; }
__device__ __forceinline__ int nxt2(int c) { return (c == 0) ? 2 : c - 1; }  // (c+2)%3

// ---------- smem layouts: pair-blocked, permuted columns (conflict-free) ----------
#define XI(c, p)  ((p)*128 + (((c)&1)*32 + ((c)>>1))*2)     // 64-col buffers
#define YI(c, p)  ((p)*320 + (((c)&1)*80 + ((c)>>1))*2)     // 160-col buffers
// 256-col hidden buffers: pair block 512 floats, col c -> slot (c&3)*64 + (c>>2)

struct Smem {
    float wbuf[3][8192];   // 3 x 32KB weight slabs
    float yT [16 * 128];
    float lvT[16 * 128];
    float uT [16 * 128];
    float ycT[16 * 320];
    float ccT[16 * 320];
    float h1A[16 * 512];
    float h1B[16 * 512];
    float ts[SEQ];
};

// ---------- first-layer slab compute: acc += A^T W over SK rows ----------
template<int COLS, int SK>
__device__ __forceinline__ void fl_slab(const float* __restrict__ AT,
                                        const float* __restrict__ Ws,
                                        int k0, u64 acc[4][4], int cg, int rg)
{
    const float4* W4 = reinterpret_cast<const float4*>(Ws) + cg;
    const float* Ap = AT + (4 * rg) * (2 * COLS);
#pragma unroll 4
    for (int kk = 0; kk < SK; ++kk) {
        const int k = k0 + kk;
        float4 w = W4[kk * 64];
        u64 w0 = bcast2(w.x), w1 = bcast2(w.y), w2 = bcast2(w.z), w3 = bcast2(w.w);
        const int m = ((k & 1) * (COLS / 2) + (k >> 1)) * 2;
#pragma unroll
        for (int q = 0; q < 4; ++q) {
            u64 a = *reinterpret_cast<const u64*>(Ap + q * (2 * COLS) + m);
            fma2(acc[q][0], a, w0); fma2(acc[q][1], a, w1);
            fma2(acc[q][2], a, w2); fma2(acc[q][3], a, w3);
        }
    }
}

// dual-stream version (two weight slabs, shared A)
template<int COLS, int SK>
__device__ __forceinline__ void fl_slab_dual(const float* __restrict__ AT,
                                             const float* __restrict__ Wsu,
                                             const float* __restrict__ Wsr,
                                             int k0, u64 aU[4][4], u64 aR[4][4],
                                             int cg, int rg)
{
    const float4* WU = reinterpret_cast<const float4*>(Wsu) + cg;
    const float4* WR = reinterpret_cast<const float4*>(Wsr) + cg;
    const float* Ap = AT + (4 * rg) * (2 * COLS);
#pragma unroll 4
    for (int kk = 0; kk < SK; ++kk) {
        const int k = k0 + kk;
        float4 wu = WU[kk * 64];
        float4 wr = WR[kk * 64];
        u64 u0 = bcast2(wu.x), u1 = bcast2(wu.y), u2 = bcast2(wu.z), u3 = bcast2(wu.w);
        u64 r0 = bcast2(wr.x), r1 = bcast2(wr.y), r2 = bcast2(wr.z), r3 = bcast2(wr.w);
        const int m = ((k & 1) * (COLS / 2) + (k >> 1)) * 2;
#pragma unroll
        for (int q = 0; q < 4; ++q) {
            u64 a = *reinterpret_cast<const u64*>(Ap + q * (2 * COLS) + m);
            fma2(aU[q][0], a, u0); fma2(aU[q][1], a, u1);
            fma2(aU[q][2], a, u2); fma2(aU[q][3], a, u3);
            fma2(aR[q][0], a, r0); fma2(aR[q][1], a, r1);
            fma2(aR[q][2], a, r2); fma2(aR[q][3], a, r3);
        }
    }
}

// ---------- second-layer slab (N=64 weights): SR rows ----------
template<int SR>
__device__ __forceinline__ void sl_slab(const float* __restrict__ A0,
                                        const float* __restrict__ A1,
                                        const float* __restrict__ Ws,
                                        int k0, int cp, u64 acc[2][2])
{
    const float2* W2 = reinterpret_cast<const float2*>(Ws) + cp;
#pragma unroll 8
    for (int kk = 0; kk < SR; ++kk) {
        const int k = k0 + kk;
        const int o = ((k & 3) * 64 + (k >> 2)) * 2;
        u64 a0 = *reinterpret_cast<const u64*>(A0 + o);
        u64 a1 = *reinterpret_cast<const u64*>(A1 + o);
        float2 w = W2[kk * 32];
        u64 wx = bcast2(w.x), wy = bcast2(w.y);
        fma2(acc[0][0], a0, wx); fma2(acc[0][1], a0, wy);
        fma2(acc[1][0], a1, wx); fma2(acc[1][1], a1, wy);
    }
}

template<int SR>
__device__ __forceinline__ void sl_slab_dual(const float* __restrict__ Aa0,
                                             const float* __restrict__ Aa1,
                                             const float* __restrict__ Ab0,
                                             const float* __restrict__ Ab1,
                                             const float* __restrict__ Wsu,
                                             const float* __restrict__ Wsr,
                                             int k0, int cp,
                                             u64 aU[2][2], u64 aR[2][2])
{
    const float2* WU = reinterpret_cast<const float2*>(Wsu) + cp;
    const float2* WR = reinterpret_cast<const float2*>(Wsr) + cp;
#pragma unroll 8
    for (int kk = 0; kk < SR; ++kk) {
        const int k = k0 + kk;
        const int o = ((k & 3) * 64 + (k >> 2)) * 2;
        u64 pa0 = *reinterpret_cast<const u64*>(Aa0 + o);
        u64 pa1 = *reinterpret_cast<const u64*>(Aa1 + o);
        u64 pb0 = *reinterpret_cast<const u64*>(Ab0 + o);
        u64 pb1 = *reinterpret_cast<const u64*>(Ab1 + o);
        float2 wu = WU[kk * 32];
        float2 wr = WR[kk * 32];
        u64 ux = bcast2(wu.x), uy = bcast2(wu.y);
        u64 rx = bcast2(wr.x), ry = bcast2(wr.y);
        fma2(aU[0][0], pa0, ux); fma2(aU[0][1], pa0, uy);
        fma2(aU[1][0], pa1, ux); fma2(aU[1][1], pa1, uy);
        fma2(aR[0][0], pb0, rx); fma2(aR[0][1], pb0, ry);
        fma2(aR[1][0], pb1, rx); fma2(aR[1][1], pb1, ry);
    }
}

// candidate layer 2 slab (N=128): two col groups per thread
template<int SR>
__device__ __forceinline__ void f_slab(const float* __restrict__ A0,
                                       const float* __restrict__ A1,
                                       const float* __restrict__ Ws,
                                       int k0, int cp, u64 aS[2][2], u64 aD[2][2])
{
    const float2* W2 = reinterpret_cast<const float2*>(Ws);
#pragma unroll 8
    for (int kk = 0; kk < SR; ++kk) {
        const int k = k0 + kk;
        const int o = ((k & 3) * 64 + (k >> 2)) * 2;
        u64 a0 = *reinterpret_cast<const u64*>(A0 + o);
        u64 a1 = *reinterpret_cast<const u64*>(A1 + o);
        float2 wl = W2[kk * 64 + cp];
        float2 wh = W2[kk * 64 + 32 + cp];
        u64 wlx = bcast2(wl.x), wly = bcast2(wl.y);
        u64 whx = bcast2(wh.x), why = bcast2(wh.y);
        fma2(aS[0][0], a0, wlx); fma2(aS[0][1], a0, wly);
        fma2(aS[1][0], a1, wlx); fma2(aS[1][1], a1, wly);
        fma2(aD[0][0], a0, whx); fma2(aD[0][1], a0, why);
        fma2(aD[1][0], a1, whx); fma2(aD[1][1], a1, why);
    }
}

__global__ __launch_bounds__(NTH, 1)
void ode_rnn_kernel(const float* __restrict__ data,
                    const float* __restrict__ tsteps,
                    const float* __restrict__ Wo1, const float* __restrict__ bo1,
                    const float* __restrict__ Wo2, const float* __restrict__ bo2,
                    const float* __restrict__ Wu1, const float* __restrict__ bu1,
                    const float* __restrict__ Wu2, const float* __restrict__ bu2,
                    const float* __restrict__ Wr1, const float* __restrict__ br1,
                    const float* __restrict__ Wr2, const float* __restrict__ br2,
                    const float* __restrict__ Wn1, const float* __restrict__ bn1,
                    const float* __restrict__ Wn2, const float* __restrict__ bn2,
                    float* __restrict__ out)
{
    extern __shared__ float smem_raw[];
    Smem* S = reinterpret_cast<Smem*>(smem_raw);
    const int tid = threadIdx.x;
    const int traj0 = blockIdx.x * TM;

    const int cg  = tid & 63;          // first-layer cols 4cg..4cg+3
    const int rg  = tid >> 6;          // first-layer pair quad 0..3
    const int cp  = tid & 31;          // second-layer col-pair
    const int rp0 = (tid >> 5) * 2;    // second-layer pairs rp0, rp0+1

    for (int i = tid; i < 16 * 128; i += NTH) { S->yT[i] = 0.f; S->lvT[i] = 0.f; }
    for (int i = tid; i < SEQ; i += NTH) S->ts[i] = tsteps[i];

    // pipeline prologue: slabs A0, A1 for step 0
    copy32(S->wbuf[0], Wo1, tid);        CPCOMMIT();
    copy32(S->wbuf[1], Wo1 + 8192, tid); CPCOMMIT();
    int cb = 0;   // compute-buffer index (mod 3); copy target is nxt2(cb)
    __syncthreads();

    const float* A0 = S->h1A + rp0 * 512;
    const float* A1 = A0 + 512;
    const float* B0 = S->h1B + rp0 * 512;
    const float* B1 = B0 + 512;

    for (int s = 0; s < SEQ - 1; ++s) {
        const float dt = (s == 0) ? (S->ts[1] - S->ts[0]) : (S->ts[s] - S->ts[s + 1]);

        // x prefetch (global), lv -> ycT[64:128]  (same-thread RAW vs prev F epilogue)
        float xv[4];
#pragma unroll
        for (int e = 0; e < 4; ++e) {
            int idx = tid + e * NTH;
            int r = idx >> 5, c = idx & 31;
            xv[e] = data[(size_t)(traj0 + r) * SEQ * DIN + (size_t)(s + 1) * DIN + c];
        }
#pragma unroll
        for (int p = 0; p < 2; ++p)
#pragma unroll
            for (int j = 0; j < 2; ++j) {
                int c = 2 * cp + j, pr = rp0 + p;
                u64 v = *reinterpret_cast<const u64*>(S->lvT + XI(c, pr));
                *reinterpret_cast<u64*>(S->ycT + YI(c + DLAT, pr)) = v;
            }

        // ===== Phase A: ODE L1 (2 slabs of 32 rows) =====
        u64 aA[4][4];
#pragma unroll
        for (int q = 0; q < 4; ++q) { aA[q][0]=0; aA[q][1]=0; aA[q][2]=0; aA[q][3]=0; }

        CPWAIT1(); __syncthreads();
        copy32(S->wbuf[nxt2(cb)], Wo2, tid); CPCOMMIT();            // B0
        fl_slab<DLAT, 32>(S->yT, S->wbuf[cb], 0, aA, cg, rg);
        cb = nxt1(cb);

        CPWAIT1(); __syncthreads();
        copy32(S->wbuf[nxt2(cb)], Wo2 + 8192, tid); CPCOMMIT();     // B1
        fl_slab<DLAT, 32>(S->yT, S->wbuf[cb], 32, aA, cg, rg);
        {   // epilogue A: tanh -> h1A
            float4 b4 = reinterpret_cast<const float4*>(bo1)[cg];
            float bb[4] = {b4.x, b4.y, b4.z, b4.w};
#pragma unroll
            for (int q = 0; q < 4; ++q)
#pragma unroll
                for (int j = 0; j < 4; ++j) {
                    float2 v = unpk(aA[q][j]);
                    v.x = tanh_f(v.x + bb[j]); v.y = tanh_f(v.y + bb[j]);
                    *reinterpret_cast<u64*>(S->h1A + (4 * rg + q) * 512 + (j * 64 + cg) * 2) = pk2(v.x, v.y);
                }
        }
#pragma unroll
        for (int e = 0; e < 4; ++e) {     // stage x -> ycT/ccT[128:160]
            int idx = tid + e * NTH;
            int r = idx >> 5, c = idx & 31;
            int a = YI(2 * DLAT + c, r >> 1) + (r & 1);
            S->ycT[a] = xv[e];
            S->ccT[a] = xv[e];
        }
        cb = nxt1(cb);

        // ===== Phase B: ODE L2 (2 slabs of 128 rows) =====
        u64 aB[2][2];
        aB[0][0]=0; aB[0][1]=0; aB[1][0]=0; aB[1][1]=0;

        CPWAIT1(); __syncthreads();
        copy16x2(S->wbuf[nxt2(cb)], Wu1, Wr1, tid); CPCOMMIT();     // C0
        sl_slab<128>(A0, A1, S->wbuf[cb], 0, cp, aB);
        cb = nxt1(cb);

        CPWAIT1(); __syncthreads();
        copy16x2(S->wbuf[nxt2(cb)], Wu1 + 4096, Wr1 + 4096, tid); CPCOMMIT(); // C1
        sl_slab<128>(A0, A1, S->wbuf[cb], 128, cp, aB);
        {   // epilogue B: ycT[0:64] = y + (o+b)*dt
            float2 bb = reinterpret_cast<const float2*>(bo2)[cp];
            float bj[2] = {bb.x, bb.y};
#pragma unroll
            for (int p = 0; p < 2; ++p)
#pragma unroll
                for (int j = 0; j < 2; ++j) {
                    int c = 2 * cp + j, pr = rp0 + p;
                    float2 o = unpk(aB[p][j]);
                    float2 y = unpk(*reinterpret_cast<const u64*>(S->yT + XI(c, pr)));
                    float rx = fmaf(o.x + bj[j], dt, y.x);
                    float ry = fmaf(o.y + bj[j], dt, y.y);
                    *reinterpret_cast<u64*>(S->ycT + YI(c, pr)) = pk2(rx, ry);
                }
        }
        cb = nxt1(cb);

        // ===== Phase C: update+reset L1 (10 dual slabs of 16 rows) =====
        u64 aU[4][4], aR[4][4];
#pragma unroll
        for (int q = 0; q < 4; ++q)
#pragma unroll
            for (int j = 0; j < 4; ++j) { aU[q][j] = 0; aR[q][j] = 0; }
#pragma unroll 1
        for (int ci = 0; ci < 10; ++ci) {
            CPWAIT1(); __syncthreads();
            const float* sa = (ci <= 7) ? Wu1 + (ci + 2) * 4096 : Wu2 + (ci - 8) * 4096;
            const float* sb = (ci <= 7) ? Wr1 + (ci + 2) * 4096 : Wr2 + (ci - 8) * 4096;
            copy16x2(S->wbuf[nxt2(cb)], sa, sb, tid); CPCOMMIT();
            fl_slab_dual<INDIM, 16>(S->ycT, S->wbuf[cb], S->wbuf[cb] + 4096,
                                    16 * ci, aU, aR, cg, rg);
            if (ci == 9) {   // epilogue C: tanh -> h1A, h1B
                float4 c4 = reinterpret_cast<const float4*>(bu1)[cg];
                float4 d4 = reinterpret_cast<const float4*>(br1)[cg];
                float ca[4] = {c4.x, c4.y, c4.z, c4.w};
                float da[4] = {d4.x, d4.y, d4.z, d4.w};
#pragma unroll
                for (int q = 0; q < 4; ++q)
#pragma unroll
                    for (int j = 0; j < 4; ++j) {
                        float2 v = unpk(aU[q][j]);
                        v.x = tanh_f(v.x + ca[j]); v.y = tanh_f(v.y + ca[j]);
                        *reinterpret_cast<u64*>(S->h1A + (4 * rg + q) * 512 + (j * 64 + cg) * 2) = pk2(v.x, v.y);
                        float2 w = unpk(aR[q][j]);
                        w.x = tanh_f(w.x + da[j]); w.y = tanh_f(w.y + da[j]);
                        *reinterpret_cast<u64*>(S->h1B + (4 * rg + q) * 512 + (j * 64 + cg) * 2) = pk2(w.x, w.y);
                    }
            }
            cb = nxt1(cb);
        }

        // ===== Phase D: update+reset L2 (4 dual slabs of 64 rows) =====
        u64 dU[2][2], dR[2][2];
        dU[0][0]=0; dU[0][1]=0; dU[1][0]=0; dU[1][1]=0;
        dR[0][0]=0; dR[0][1]=0; dR[1][0]=0; dR[1][1]=0;
#pragma unroll 1
        for (int di = 0; di < 4; ++di) {
            CPWAIT1(); __syncthreads();
            if (di < 2) {
                copy16x2(S->wbuf[nxt2(cb)], Wu2 + (di + 2) * 4096, Wr2 + (di + 2) * 4096, tid);
            } else {
                copy32(S->wbuf[nxt2(cb)], Wn1 + (di - 2) * 8192, tid);   // E0, E1
            }
            CPCOMMIT();
            sl_slab_dual<64>(A0, A1, B0, B1, S->wbuf[cb], S->wbuf[cb] + 4096,
                             64 * di, cp, dU, dR);
            if (di == 3) {   // epilogue D -> uT, ccT[0:128]
                float2 bu = reinterpret_cast<const float2*>(bu2)[cp];
                float2 br = reinterpret_cast<const float2*>(br2)[cp];
                float buj[2] = {bu.x, bu.y};
                float brj[2] = {br.x, br.y};
#pragma unroll
                for (int p = 0; p < 2; ++p)
#pragma unroll
                    for (int j = 0; j < 2; ++j) {
                        int c = 2 * cp + j, pr = rp0 + p;
                        float2 vu = unpk(dU[p][j]);
                        *reinterpret_cast<u64*>(S->uT + XI(c, pr)) =
                            pk2(sigmoid_f(vu.x + buj[j]), sigmoid_f(vu.y + buj[j]));
                        float2 vr = unpk(dR[p][j]);
                        u64 rpair = pk2(sigmoid_f(vr.x + brj[j]), sigmoid_f(vr.y + brj[j]));
                        u64 ylo = *reinterpret_cast<const u64*>(S->ycT + YI(c, pr));
                        u64 yhi = *reinterpret_cast<const u64*>(S->ycT + YI(c + DLAT, pr));
                        *reinterpret_cast<u64*>(S->ccT + YI(c, pr))        = mul2(ylo, rpair);
                        *reinterpret_cast<u64*>(S->ccT + YI(c + DLAT, pr)) = mul2(yhi, rpair);
                    }
            }
            cb = nxt1(cb);
        }

        // ===== Phase E: candidate L1 (5 slabs of 32 rows) =====
        u64 aE[4][4];
#pragma unroll
        for (int q = 0; q < 4; ++q) { aE[q][0]=0; aE[q][1]=0; aE[q][2]=0; aE[q][3]=0; }
#pragma unroll 1
        for (int ei = 0; ei < 5; ++ei) {
            CPWAIT1(); __syncthreads();
            const float* sp = (ei <= 2) ? Wn1 + (ei + 2) * 8192 : Wn2 + (ei - 3) * 8192;
            copy32(S->wbuf[nxt2(cb)], sp, tid); CPCOMMIT();
            fl_slab<INDIM, 32>(S->ccT, S->wbuf[cb], 32 * ei, aE, cg, rg);
            if (ei == 4) {   // epilogue E: tanh -> h1A
                float4 b4 = reinterpret_cast<const float4*>(bn1)[cg];
                float bb[4] = {b4.x, b4.y, b4.z, b4.w};
#pragma unroll
                for (int q = 0; q < 4; ++q)
#pragma unroll
                    for (int j = 0; j < 4; ++j) {
                        float2 v = unpk(aE[q][j]);
                        v.x = tanh_f(v.x + bb[j]); v.y = tanh_f(v.y + bb[j]);
                        *reinterpret_cast<u64*>(S->h1A + (4 * rg + q) * 512 + (j * 64 + cg) * 2) = pk2(v.x, v.y);
                    }
            }
            cb = nxt1(cb);
        }

        // ===== Phase F: candidate L2 (4 slabs of 64 rows) + state update =====
        u64 fS[2][2], fD[2][2];
        fS[0][0]=0; fS[0][1]=0; fS[1][0]=0; fS[1][1]=0;
        fD[0][0]=0; fD[0][1]=0; fD[1][0]=0; fD[1][1]=0;
#pragma unroll 1
        for (int fi = 0; fi < 4; ++fi) {
            CPWAIT1(); __syncthreads();
            const float* sp = (fi < 2) ? Wn2 + (fi + 2) * 8192 : Wo1 + (fi - 2) * 8192;
            copy32(S->wbuf[nxt2(cb)], sp, tid); CPCOMMIT();   // F2,F3 then next-step A0,A1
            f_slab<64>(A0, A1, S->wbuf[cb], 64 * fi, cp, fS, fD);
            if (fi == 3) {   // epilogue F: fused state update
                float2 bl = reinterpret_cast<const float2*>(bn2)[cp];
                float2 bh = *reinterpret_cast<const float2*>(bn2 + DLAT + 2 * cp);
                float blj[2] = {bl.x, bl.y};
                float bhj[2] = {bh.x, bh.y};
#pragma unroll
                for (int p = 0; p < 2; ++p)
#pragma unroll
                    for (int j = 0; j < 2; ++j) {
                        int c = 2 * cp + j, pr = rp0 + p;
                        float2 ns = unpk(fS[p][j]);
                        ns.x += blj[j]; ns.y += blj[j];
                        float2 nd = unpk(fD[p][j]);
                        nd.x = fabsf(nd.x + bhj[j]); nd.y = fabsf(nd.y + bhj[j]);
                        float2 uu = unpk(*reinterpret_cast<const u64*>(S->uT + XI(c, pr)));
                        float2 yo = unpk(*reinterpret_cast<const u64*>(S->ycT + YI(c, pr)));
                        float2 lo = unpk(*reinterpret_cast<const u64*>(S->lvT + XI(c, pr)));
                        float ny0 = (1.f - uu.x) * ns.x + uu.x * yo.x;
                        float ny1 = (1.f - uu.y) * ns.y + uu.y * yo.y;
                        float nl0 = (1.f - uu.x) * nd.x + uu.x * lo.x;
                        float nl1 = (1.f - uu.y) * nd.y + uu.y * lo.y;
                        *reinterpret_cast<u64*>(S->yT + XI(c, pr))  = pk2(ny0, ny1);
                        *reinterpret_cast<u64*>(S->lvT + XI(c, pr)) = pk2(nl0, nl1);
                    }
            }
            cb = nxt1(cb);
        }
    }

    CPWAIT0(); __syncthreads();

    // ===== output: yi (4096x64) then yi_logvar (4096x64) =====
    for (int i = tid; i < TM * DLAT; i += NTH) {
        int r = i >> 6, c = i & 63;
        int a = XI(c, r >> 1) + (r & 1);
        out[(size_t)(traj0 + r) * DLAT + c] = S->yT[a];
        out[(size_t)NT * DLAT + (size_t)(traj0 + r) * DLAT + c] = S->lvT[a];
    }
}

extern "C" void kernel_launch(void* const* d_in, const int* in_sizes, int n_in,
                              void* d_out, int out_size) {
    const float* data = (const float*)d_in[0];
    const float* ts   = (const float*)d_in[1];
    const float* Wo1  = (const float*)d_in[2];
    const float* bo1  = (const float*)d_in[3];
    const float* Wo2  = (const float*)d_in[4];
    const float* bo2  = (const float*)d_in[5];
    const float* Wu1  = (const float*)d_in[6];
    const float* bu1  = (const float*)d_in[7];
    const float* Wu2  = (const float*)d_in[8];
    const float* bu2  = (const float*)d_in[9];
    const float* Wr1  = (const float*)d_in[10];
    const float* br1  = (const float*)d_in[11];
    const float* Wr2  = (const float*)d_in[12];
    const float* br2  = (const float*)d_in[13];
    const float* Wn1  = (const float*)d_in[14];
    const float* bn1  = (const float*)d_in[15];
    const float* Wn2  = (const float*)d_in[16];
    const float* bn2  = (const float*)d_in[17];
    float* out = (float*)d_out;

    const int smem = (int)sizeof(Smem);
    cudaFuncSetAttribute(ode_rnn_kernel,
                         cudaFuncAttributeMaxDynamicSharedMemorySize, smem);
    ode_rnn_kernel<<<NT / TM, NTH, smem>>>(
        data, ts, Wo1, bo1, Wo2, bo2, Wu1, bu1, Wu2, bu2,
        Wr1, br1, Wr2, br2, Wn1, bn1, Wn2, bn2, out);
}

// round 17
// speedup vs baseline: 1.1305x; 1.0127x over previous
#include <cuda_runtime.h>
#include <math.h>

#define NT    4096
#define SEQ   128
#define DIN   32
#define DLAT  64
#define NU    256
#define INDIM 160
#define TM    32
#define NTH   256

typedef unsigned long long u64;
typedef ulonglong2 u64x2;

// ---------- packed f32x2 helpers ----------
__device__ __forceinline__ u64 bcast2(float a) {
    u64 r; asm("mov.b64 %0, {%1, %1};" : "=l"(r) : "f"(a)); return r;
}
__device__ __forceinline__ u64 pk2(float x, float y) {
    u64 r; asm("mov.b64 %0, {%1, %2};" : "=l"(r) : "f"(x), "f"(y)); return r;
}
__device__ __forceinline__ float2 unpk(u64 v) {
    float2 f; asm("mov.b64 {%0, %1}, %2;" : "=f"(f.x), "=f"(f.y) : "l"(v)); return f;
}
__device__ __forceinline__ void fma2(u64& d, u64 a, u64 b) {
    asm("fma.rn.f32x2 %0, %1, %2, %0;" : "+l"(d) : "l"(a), "l"(b));
}
__device__ __forceinline__ u64 mul2(u64 a, u64 b) {
    u64 d; asm("mul.rn.f32x2 %0, %1, %2;" : "=l"(d) : "l"(a), "l"(b)); return d;
}
// fast activations on the MUFU pipe
__device__ __forceinline__ float tanh_f(float x) {
    return 1.0f - __fdividef(2.0f, __expf(2.0f * x) + 1.0f);
}
__device__ __forceinline__ float sigmoid_f(float x) {
    return __fdividef(1.0f, 1.0f + __expf(-x));
}

// ---------- cp.async helpers ----------
__device__ __forceinline__ void cpa16(unsigned d, const float* s) {
    asm volatile("cp.async.cg.shared.global [%0], [%1], 16;" :: "r"(d), "l"(s));
}
#define CPCOMMIT() asm volatile("cp.async.commit_group;")
#define CPWAIT1()  asm volatile("cp.async.wait_group 1;")
#define CPWAIT0()  asm volatile("cp.async.wait_group 0;")

// 32KB slab from one source
__device__ __forceinline__ void copy32(float* dst, const float* __restrict__ src, int tid) {
    unsigned d = (unsigned)__cvta_generic_to_shared(dst) + tid * 16;
    const float* s = src + tid * 4;
#pragma unroll
    for (int i = 0; i < 8; ++i) cpa16(d + i * 4096, s + i * 1024);
}
// 16KB + 16KB from two sources
__device__ __forceinline__ void copy16x2(float* dst, const float* __restrict__ sa,
                                         const float* __restrict__ sb, int tid) {
    unsigned d = (unsigned)__cvta_generic_to_shared(dst) + tid * 16;
#pragma unroll
    for (int i = 0; i < 4; ++i) cpa16(d + i * 4096, sa + tid * 4 + i * 1024);
#pragma unroll
    for (int i = 0; i < 4; ++i) cpa16(d + 16384 + i * 4096, sb + tid * 4 + i * 1024);
}

__device__ __forceinline__ int nxt1(int c) { return (c == 2) ? 0 : c + 1; }
__device__ __forceinline__ int nxt2(int c) { return (c == 0) ? 2 : c - 1; }

// ---------- smem layouts: pair-blocked, permuted columns (conflict-free) ----------
#define XI(c, p)  ((p)*128 + (((c)&1)*32 + ((c)>>1))*2)     // 64-col buffers
#define YI(c, p)  ((p)*320 + (((c)&1)*80 + ((c)>>1))*2)     // 160-col buffers
// 256-col hidden buffers: pair block 512 floats, col c -> slot (c&3)*64 + (c>>2)

struct Smem {
    float wbuf[3][8192];   // 3 x 32KB weight slabs
    float yT [16 * 128];
    float lvT[16 * 128];
    float uT [16 * 128];
    float ycT[16 * 320];
    float ccT[16 * 320];
    float h1A[16 * 512];
    float h1B[16 * 512];
    float ts[SEQ];
};

// ---------- first-layer slab: paired-k A loads (LDS.128 covers k, k+2) ----------
// k0 must be even. Global k = k0 + 2t + jj ; A slot pairs (t, t+1) are contiguous.
template<int COLS, int SK>
__device__ __forceinline__ void fl_slab(const float* __restrict__ AT,
                                        const float* __restrict__ Ws,
                                        int k0, u64 acc[4][4], int cg, int rg)
{
    const float4* W4 = reinterpret_cast<const float4*>(Ws) + cg;
    const float* Ap = AT + (4 * rg) * (2 * COLS);
    const int kh = k0 >> 1;
#pragma unroll
    for (int jj = 0; jj < 2; ++jj) {
#pragma unroll 2
        for (int t = 0; t < SK / 2; t += 2) {
            float4 wA = W4[(2 * t + jj) * 64];
            float4 wB = W4[(2 * t + 2 + jj) * 64];
            u64 a0 = bcast2(wA.x), a1 = bcast2(wA.y), a2 = bcast2(wA.z), a3 = bcast2(wA.w);
            u64 b0 = bcast2(wB.x), b1 = bcast2(wB.y), b2 = bcast2(wB.z), b3 = bcast2(wB.w);
            const int m = (jj * (COLS / 2) + kh + t) * 2;
#pragma unroll
            for (int q = 0; q < 4; ++q) {
                u64x2 a = *reinterpret_cast<const u64x2*>(Ap + q * (2 * COLS) + m);
                fma2(acc[q][0], a.x, a0); fma2(acc[q][1], a.x, a1);
                fma2(acc[q][2], a.x, a2); fma2(acc[q][3], a.x, a3);
                fma2(acc[q][0], a.y, b0); fma2(acc[q][1], a.y, b1);
                fma2(acc[q][2], a.y, b2); fma2(acc[q][3], a.y, b3);
            }
        }
    }
}

// dual-stream version (two weight slabs, shared A)
template<int COLS, int SK>
__device__ __forceinline__ void fl_slab_dual(const float* __restrict__ AT,
                                             const float* __restrict__ Wsu,
                                             const float* __restrict__ Wsr,
                                             int k0, u64 aU[4][4], u64 aR[4][4],
                                             int cg, int rg)
{
    const float4* WU = reinterpret_cast<const float4*>(Wsu) + cg;
    const float4* WR = reinterpret_cast<const float4*>(Wsr) + cg;
    const float* Ap = AT + (4 * rg) * (2 * COLS);
    const int kh = k0 >> 1;
#pragma unroll
    for (int jj = 0; jj < 2; ++jj) {
#pragma unroll 1
        for (int t = 0; t < SK / 2; t += 2) {
            float4 uA = WU[(2 * t + jj) * 64];
            float4 uB = WU[(2 * t + 2 + jj) * 64];
            float4 rA = WR[(2 * t + jj) * 64];
            float4 rB = WR[(2 * t + 2 + jj) * 64];
            u64 ua0 = bcast2(uA.x), ua1 = bcast2(uA.y), ua2 = bcast2(uA.z), ua3 = bcast2(uA.w);
            u64 ub0 = bcast2(uB.x), ub1 = bcast2(uB.y), ub2 = bcast2(uB.z), ub3 = bcast2(uB.w);
            u64 ra0 = bcast2(rA.x), ra1 = bcast2(rA.y), ra2 = bcast2(rA.z), ra3 = bcast2(rA.w);
            u64 rb0 = bcast2(rB.x), rb1 = bcast2(rB.y), rb2 = bcast2(rB.z), rb3 = bcast2(rB.w);
            const int m = (jj * (COLS / 2) + kh + t) * 2;
#pragma unroll
            for (int q = 0; q < 4; ++q) {
                u64x2 a = *reinterpret_cast<const u64x2*>(Ap + q * (2 * COLS) + m);
                fma2(aU[q][0], a.x, ua0); fma2(aU[q][1], a.x, ua1);
                fma2(aU[q][2], a.x, ua2); fma2(aU[q][3], a.x, ua3);
                fma2(aU[q][0], a.y, ub0); fma2(aU[q][1], a.y, ub1);
                fma2(aU[q][2], a.y, ub2); fma2(aU[q][3], a.y, ub3);
                fma2(aR[q][0], a.x, ra0); fma2(aR[q][1], a.x, ra1);
                fma2(aR[q][2], a.x, ra2); fma2(aR[q][3], a.x, ra3);
                fma2(aR[q][0], a.y, rb0); fma2(aR[q][1], a.y, rb1);
                fma2(aR[q][2], a.y, rb2); fma2(aR[q][3], a.y, rb3);
            }
        }
    }
}

// ---------- second-layer slab (N=64): paired-k A loads (k, k+4) ----------
// k0 multiple of 4.
template<int SR>
__device__ __forceinline__ void sl_slab(const float* __restrict__ A0,
                                        const float* __restrict__ A1,
                                        const float* __restrict__ Ws,
                                        int k0, int cp, u64 acc[2][2])
{
    const float2* W2 = reinterpret_cast<const float2*>(Ws) + cp;
    const int base = k0 >> 2;
#pragma unroll 4
    for (int t = 0; t < SR / 4; t += 2) {
#pragma unroll
        for (int j = 0; j < 4; ++j) {
            const int o = (j * 64 + base + t) * 2;
            u64x2 a0 = *reinterpret_cast<const u64x2*>(A0 + o);   // k=k0+4t+j, k0+4t+4+j
            u64x2 a1 = *reinterpret_cast<const u64x2*>(A1 + o);
            float2 wA = W2[(4 * t + j) * 32];
            float2 wB = W2[(4 * (t + 1) + j) * 32];
            u64 wAx = bcast2(wA.x), wAy = bcast2(wA.y);
            u64 wBx = bcast2(wB.x), wBy = bcast2(wB.y);
            fma2(acc[0][0], a0.x, wAx); fma2(acc[0][1], a0.x, wAy);
            fma2(acc[1][0], a1.x, wAx); fma2(acc[1][1], a1.x, wAy);
            fma2(acc[0][0], a0.y, wBx); fma2(acc[0][1], a0.y, wBy);
            fma2(acc[1][0], a1.y, wBx); fma2(acc[1][1], a1.y, wBy);
        }
    }
}

template<int SR>
__device__ __forceinline__ void sl_slab_dual(const float* __restrict__ Aa0,
                                             const float* __restrict__ Aa1,
                                             const float* __restrict__ Ab0,
                                             const float* __restrict__ Ab1,
                                             const float* __restrict__ Wsu,
                                             const float* __restrict__ Wsr,
                                             int k0, int cp,
                                             u64 aU[2][2], u64 aR[2][2])
{
    const float2* WU = reinterpret_cast<const float2*>(Wsu) + cp;
    const float2* WR = reinterpret_cast<const float2*>(Wsr) + cp;
    const int base = k0 >> 2;
#pragma unroll 2
    for (int t = 0; t < SR / 4; t += 2) {
#pragma unroll
        for (int j = 0; j < 4; ++j) {
            const int o = (j * 64 + base + t) * 2;
            u64x2 pa0 = *reinterpret_cast<const u64x2*>(Aa0 + o);
            u64x2 pa1 = *reinterpret_cast<const u64x2*>(Aa1 + o);
            u64x2 pb0 = *reinterpret_cast<const u64x2*>(Ab0 + o);
            u64x2 pb1 = *reinterpret_cast<const u64x2*>(Ab1 + o);
            float2 uA = WU[(4 * t + j) * 32];
            float2 uB = WU[(4 * (t + 1) + j) * 32];
            float2 rA = WR[(4 * t + j) * 32];
            float2 rB = WR[(4 * (t + 1) + j) * 32];
            u64 uAx = bcast2(uA.x), uAy = bcast2(uA.y);
            u64 uBx = bcast2(uB.x), uBy = bcast2(uB.y);
            u64 rAx = bcast2(rA.x), rAy = bcast2(rA.y);
            u64 rBx = bcast2(rB.x), rBy = bcast2(rB.y);
            fma2(aU[0][0], pa0.x, uAx); fma2(aU[0][1], pa0.x, uAy);
            fma2(aU[1][0], pa1.x, uAx); fma2(aU[1][1], pa1.x, uAy);
            fma2(aU[0][0], pa0.y, uBx); fma2(aU[0][1], pa0.y, uBy);
            fma2(aU[1][0], pa1.y, uBx); fma2(aU[1][1], pa1.y, uBy);
            fma2(aR[0][0], pb0.x, rAx); fma2(aR[0][1], pb0.x, rAy);
            fma2(aR[1][0], pb1.x, rAx); fma2(aR[1][1], pb1.x, rAy);
            fma2(aR[0][0], pb0.y, rBx); fma2(aR[0][1], pb0.y, rBy);
            fma2(aR[1][0], pb1.y, rBx); fma2(aR[1][1], pb1.y, rBy);
        }
    }
}

// candidate layer 2 slab (N=128): paired-k A loads
template<int SR>
__device__ __forceinline__ void f_slab(const float* __restrict__ A0,
                                       const float* __restrict__ A1,
                                       const float* __restrict__ Ws,
                                       int k0, int cp, u64 aS[2][2], u64 aD[2][2])
{
    const float2* W2 = reinterpret_cast<const float2*>(Ws);
    const int base = k0 >> 2;
#pragma unroll 2
    for (int t = 0; t < SR / 4; t += 2) {
#pragma unroll
        for (int j = 0; j < 4; ++j) {
            const int o = (j * 64 + base + t) * 2;
            u64x2 a0 = *reinterpret_cast<const u64x2*>(A0 + o);
            u64x2 a1 = *reinterpret_cast<const u64x2*>(A1 + o);
            float2 lA = W2[(4 * t + j) * 64 + cp];
            float2 hA = W2[(4 * t + j) * 64 + 32 + cp];
            float2 lB = W2[(4 * (t + 1) + j) * 64 + cp];
            float2 hB = W2[(4 * (t + 1) + j) * 64 + 32 + cp];
            u64 lAx = bcast2(lA.x), lAy = bcast2(lA.y);
            u64 hAx = bcast2(hA.x), hAy = bcast2(hA.y);
            u64 lBx = bcast2(lB.x), lBy = bcast2(lB.y);
            u64 hBx = bcast2(hB.x), hBy = bcast2(hB.y);
            fma2(aS[0][0], a0.x, lAx); fma2(aS[0][1], a0.x, lAy);
            fma2(aS[1][0], a1.x, lAx); fma2(aS[1][1], a1.x, lAy);
            fma2(aD[0][0], a0.x, hAx); fma2(aD[0][1], a0.x, hAy);
            fma2(aD[1][0], a1.x, hAx); fma2(aD[1][1], a1.x, hAy);
            fma2(aS[0][0], a0.y, lBx); fma2(aS[0][1], a0.y, lBy);
            fma2(aS[1][0], a1.y, lBx); fma2(aS[1][1], a1.y, lBy);
            fma2(aD[0][0], a0.y, hBx); fma2(aD[0][1], a0.y, hBy);
            fma2(aD[1][0], a1.y, hBx); fma2(aD[1][1], a1.y, hBy);
        }
    }
}

__global__ __launch_bounds__(NTH, 1)
void ode_rnn_kernel(const float* __restrict__ data,
                    const float* __restrict__ tsteps,
                    const float* __restrict__ Wo1, const float* __restrict__ bo1,
                    const float* __restrict__ Wo2, const float* __restrict__ bo2,
                    const float* __restrict__ Wu1, const float* __restrict__ bu1,
                    const float* __restrict__ Wu2, const float* __restrict__ bu2,
                    const float* __restrict__ Wr1, const float* __restrict__ br1,
                    const float* __restrict__ Wr2, const float* __restrict__ br2,
                    const float* __restrict__ Wn1, const float* __restrict__ bn1,
                    const float* __restrict__ Wn2, const float* __restrict__ bn2,
                    float* __restrict__ out)
{
    extern __shared__ float smem_raw[];
    Smem* S = reinterpret_cast<Smem*>(smem_raw);
    const int tid = threadIdx.x;
    const int traj0 = blockIdx.x * TM;

    const int cg  = tid & 63;          // first-layer cols 4cg..4cg+3
    const int rg  = tid >> 6;          // first-layer pair quad 0..3
    const int cp  = tid & 31;          // second-layer col-pair
    const int rp0 = (tid >> 5) * 2;    // second-layer pairs rp0, rp0+1

    for (int i = tid; i < 16 * 128; i += NTH) { S->yT[i] = 0.f; S->lvT[i] = 0.f; }
    for (int i = tid; i < SEQ; i += NTH) S->ts[i] = tsteps[i];

    // pipeline prologue: slabs A0, A1 for step 0
    copy32(S->wbuf[0], Wo1, tid);        CPCOMMIT();
    copy32(S->wbuf[1], Wo1 + 8192, tid); CPCOMMIT();
    int cb = 0;   // compute-buffer index (mod 3); copy target is nxt2(cb)
    __syncthreads();

    const float* A0 = S->h1A + rp0 * 512;
    const float* A1 = A0 + 512;
    const float* B0 = S->h1B + rp0 * 512;
    const float* B1 = B0 + 512;

    for (int s = 0; s < SEQ - 1; ++s) {
        const float dt = (s == 0) ? (S->ts[1] - S->ts[0]) : (S->ts[s] - S->ts[s + 1]);

        // x prefetch (global), lv -> ycT[64:128]  (same-thread RAW vs prev F epilogue)
        float xv[4];
#pragma unroll
        for (int e = 0; e < 4; ++e) {
            int idx = tid + e * NTH;
            int r = idx >> 5, c = idx & 31;
            xv[e] = data[(size_t)(traj0 + r) * SEQ * DIN + (size_t)(s + 1) * DIN + c];
        }
#pragma unroll
        for (int p = 0; p < 2; ++p)
#pragma unroll
            for (int j = 0; j < 2; ++j) {
                int c = 2 * cp + j, pr = rp0 + p;
                u64 v = *reinterpret_cast<const u64*>(S->lvT + XI(c, pr));
                *reinterpret_cast<u64*>(S->ycT + YI(c + DLAT, pr)) = v;
            }

        // ===== Phase A: ODE L1 (2 slabs of 32 rows) =====
        u64 aA[4][4];
#pragma unroll
        for (int q = 0; q < 4; ++q) { aA[q][0]=0; aA[q][1]=0; aA[q][2]=0; aA[q][3]=0; }

        CPWAIT1(); __syncthreads();
        copy32(S->wbuf[nxt2(cb)], Wo2, tid); CPCOMMIT();            // B0
        fl_slab<DLAT, 32>(S->yT, S->wbuf[cb], 0, aA, cg, rg);
        cb = nxt1(cb);

        CPWAIT1(); __syncthreads();
        copy32(S->wbuf[nxt2(cb)], Wo2 + 8192, tid); CPCOMMIT();     // B1
        fl_slab<DLAT, 32>(S->yT, S->wbuf[cb], 32, aA, cg, rg);
        {   // epilogue A: tanh -> h1A
            float4 b4 = reinterpret_cast<const float4*>(bo1)[cg];
            float bb[4] = {b4.x, b4.y, b4.z, b4.w};
#pragma unroll
            for (int q = 0; q < 4; ++q)
#pragma unroll
                for (int j = 0; j < 4; ++j) {
                    float2 v = unpk(aA[q][j]);
                    v.x = tanh_f(v.x + bb[j]); v.y = tanh_f(v.y + bb[j]);
                    *reinterpret_cast<u64*>(S->h1A + (4 * rg + q) * 512 + (j * 64 + cg) * 2) = pk2(v.x, v.y);
                }
        }
#pragma unroll
        for (int e = 0; e < 4; ++e) {     // stage x -> ycT/ccT[128:160]
            int idx = tid + e * NTH;
            int r = idx >> 5, c = idx & 31;
            int a = YI(2 * DLAT + c, r >> 1) + (r & 1);
            S->ycT[a] = xv[e];
            S->ccT[a] = xv[e];
        }
        cb = nxt1(cb);

        // ===== Phase B: ODE L2 (2 slabs of 128 rows) =====
        u64 aB[2][2];
        aB[0][0]=0; aB[0][1]=0; aB[1][0]=0; aB[1][1]=0;

        CPWAIT1(); __syncthreads();
        copy16x2(S->wbuf[nxt2(cb)], Wu1, Wr1, tid); CPCOMMIT();     // C0
        sl_slab<128>(A0, A1, S->wbuf[cb], 0, cp, aB);
        cb = nxt1(cb);

        CPWAIT1(); __syncthreads();
        copy16x2(S->wbuf[nxt2(cb)], Wu1 + 4096, Wr1 + 4096, tid); CPCOMMIT(); // C1
        sl_slab<128>(A0, A1, S->wbuf[cb], 128, cp, aB);
        {   // epilogue B: ycT[0:64] = y + (o+b)*dt
            float2 bb = reinterpret_cast<const float2*>(bo2)[cp];
            float bj[2] = {bb.x, bb.y};
#pragma unroll
            for (int p = 0; p < 2; ++p)
#pragma unroll
                for (int j = 0; j < 2; ++j) {
                    int c = 2 * cp + j, pr = rp0 + p;
                    float2 o = unpk(aB[p][j]);
                    float2 y = unpk(*reinterpret_cast<const u64*>(S->yT + XI(c, pr)));
                    float rx = fmaf(o.x + bj[j], dt, y.x);
                    float ry = fmaf(o.y + bj[j], dt, y.y);
                    *reinterpret_cast<u64*>(S->ycT + YI(c, pr)) = pk2(rx, ry);
                }
        }
        cb = nxt1(cb);

        // ===== Phase C: update+reset L1 (10 dual slabs of 16 rows) =====
        u64 aU[4][4], aR[4][4];
#pragma unroll
        for (int q = 0; q < 4; ++q)
#pragma unroll
            for (int j = 0; j < 4; ++j) { aU[q][j] = 0; aR[q][j] = 0; }
#pragma unroll 1
        for (int ci = 0; ci < 10; ++ci) {
            CPWAIT1(); __syncthreads();
            const float* sa = (ci <= 7) ? Wu1 + (ci + 2) * 4096 : Wu2 + (ci - 8) * 4096;
            const float* sb = (ci <= 7) ? Wr1 + (ci + 2) * 4096 : Wr2 + (ci - 8) * 4096;
            copy16x2(S->wbuf[nxt2(cb)], sa, sb, tid); CPCOMMIT();
            fl_slab_dual<INDIM, 16>(S->ycT, S->wbuf[cb], S->wbuf[cb] + 4096,
                                    16 * ci, aU, aR, cg, rg);
            if (ci == 9) {   // epilogue C: tanh -> h1A, h1B
                float4 c4 = reinterpret_cast<const float4*>(bu1)[cg];
                float4 d4 = reinterpret_cast<const float4*>(br1)[cg];
                float ca[4] = {c4.x, c4.y, c4.z, c4.w};
                float da[4] = {d4.x, d4.y, d4.z, d4.w};
#pragma unroll
                for (int q = 0; q < 4; ++q)
#pragma unroll
                    for (int j = 0; j < 4; ++j) {
                        float2 v = unpk(aU[q][j]);
                        v.x = tanh_f(v.x + ca[j]); v.y = tanh_f(v.y + ca[j]);
                        *reinterpret_cast<u64*>(S->h1A + (4 * rg + q) * 512 + (j * 64 + cg) * 2) = pk2(v.x, v.y);
                        float2 w = unpk(aR[q][j]);
                        w.x = tanh_f(w.x + da[j]); w.y = tanh_f(w.y + da[j]);
                        *reinterpret_cast<u64*>(S->h1B + (4 * rg + q) * 512 + (j * 64 + cg) * 2) = pk2(w.x, w.y);
                    }
            }
            cb = nxt1(cb);
        }

        // ===== Phase D: update+reset L2 (4 dual slabs of 64 rows) =====
        u64 dU[2][2], dR[2][2];
        dU[0][0]=0; dU[0][1]=0; dU[1][0]=0; dU[1][1]=0;
        dR[0][0]=0; dR[0][1]=0; dR[1][0]=0; dR[1][1]=0;
#pragma unroll 1
        for (int di = 0; di < 4; ++di) {
            CPWAIT1(); __syncthreads();
            if (di < 2) {
                copy16x2(S->wbuf[nxt2(cb)], Wu2 + (di + 2) * 4096, Wr2 + (di + 2) * 4096, tid);
            } else {
                copy32(S->wbuf[nxt2(cb)], Wn1 + (di - 2) * 8192, tid);   // E0, E1
            }
            CPCOMMIT();
            sl_slab_dual<64>(A0, A1, B0, B1, S->wbuf[cb], S->wbuf[cb] + 4096,
                             64 * di, cp, dU, dR);
            if (di == 3) {   // epilogue D -> uT, ccT[0:128]
                float2 bu = reinterpret_cast<const float2*>(bu2)[cp];
                float2 br = reinterpret_cast<const float2*>(br2)[cp];
                float buj[2] = {bu.x, bu.y};
                float brj[2] = {br.x, br.y};
#pragma unroll
                for (int p = 0; p < 2; ++p)
#pragma unroll
                    for (int j = 0; j < 2; ++j) {
                        int c = 2 * cp + j, pr = rp0 + p;
                        float2 vu = unpk(dU[p][j]);
                        *reinterpret_cast<u64*>(S->uT + XI(c, pr)) =
                            pk2(sigmoid_f(vu.x + buj[j]), sigmoid_f(vu.y + buj[j]));
                        float2 vr = unpk(dR[p][j]);
                        u64 rpair = pk2(sigmoid_f(vr.x + brj[j]), sigmoid_f(vr.y + brj[j]));
                        u64 ylo = *reinterpret_cast<const u64*>(S->ycT + YI(c, pr));
                        u64 yhi = *reinterpret_cast<const u64*>(S->ycT + YI(c + DLAT, pr));
                        *reinterpret_cast<u64*>(S->ccT + YI(c, pr))        = mul2(ylo, rpair);
                        *reinterpret_cast<u64*>(S->ccT + YI(c + DLAT, pr)) = mul2(yhi, rpair);
                    }
            }
            cb = nxt1(cb);
        }

        // ===== Phase E: candidate L1 (5 slabs of 32 rows) =====
        u64 aE[4][4];
#pragma unroll
        for (int q = 0; q < 4; ++q) { aE[q][0]=0; aE[q][1]=0; aE[q][2]=0; aE[q][3]=0; }
#pragma unroll 1
        for (int ei = 0; ei < 5; ++ei) {
            CPWAIT1(); __syncthreads();
            const float* sp = (ei <= 2) ? Wn1 + (ei + 2) * 8192 : Wn2 + (ei - 3) * 8192;
            copy32(S->wbuf[nxt2(cb)], sp, tid); CPCOMMIT();
            fl_slab<INDIM, 32>(S->ccT, S->wbuf[cb], 32 * ei, aE, cg, rg);
            if (ei == 4) {   // epilogue E: tanh -> h1A
                float4 b4 = reinterpret_cast<const float4*>(bn1)[cg];
                float bb[4] = {b4.x, b4.y, b4.z, b4.w};
#pragma unroll
                for (int q = 0; q < 4; ++q)
#pragma unroll
                    for (int j = 0; j < 4; ++j) {
                        float2 v = unpk(aE[q][j]);
                        v.x = tanh_f(v.x + bb[j]); v.y = tanh_f(v.y + bb[j]);
                        *reinterpret_cast<u64*>(S->h1A + (4 * rg + q) * 512 + (j * 64 + cg) * 2) = pk2(v.x, v.y);
                    }
            }
            cb = nxt1(cb);
        }

        // ===== Phase F: candidate L2 (4 slabs of 64 rows) + state update =====
        u64 fS[2][2], fD[2][2];
        fS[0][0]=0; fS[0][1]=0; fS[1][0]=0; fS[1][1]=0;
        fD[0][0]=0; fD[0][1]=0; fD[1][0]=0; fD[1][1]=0;
#pragma unroll 1
        for (int fi = 0; fi < 4; ++fi) {
            CPWAIT1(); __syncthreads();
            const float* sp = (fi < 2) ? Wn2 + (fi + 2) * 8192 : Wo1 + (fi - 2) * 8192;
            copy32(S->wbuf[nxt2(cb)], sp, tid); CPCOMMIT();   // F2,F3 then next-step A0,A1
            f_slab<64>(A0, A1, S->wbuf[cb], 64 * fi, cp, fS, fD);
            if (fi == 3) {   // epilogue F: fused state update
                float2 bl = reinterpret_cast<const float2*>(bn2)[cp];
                float2 bh = *reinterpret_cast<const float2*>(bn2 + DLAT + 2 * cp);
                float blj[2] = {bl.x, bl.y};
                float bhj[2] = {bh.x, bh.y};
#pragma unroll
                for (int p = 0; p < 2; ++p)
#pragma unroll
                    for (int j = 0; j < 2; ++j) {
                        int c = 2 * cp + j, pr = rp0 + p;
                        float2 ns = unpk(fS[p][j]);
                        ns.x += blj[j]; ns.y += blj[j];
                        float2 nd = unpk(fD[p][j]);
                        nd.x = fabsf(nd.x + bhj[j]); nd.y = fabsf(nd.y + bhj[j]);
                        float2 uu = unpk(*reinterpret_cast<const u64*>(S->uT + XI(c, pr)));
                        float2 yo = unpk(*reinterpret_cast<const u64*>(S->ycT + YI(c, pr)));
                        float2 lo = unpk(*reinterpret_cast<const u64*>(S->lvT + XI(c, pr)));
                        float ny0 = (1.f - uu.x) * ns.x + uu.x * yo.x;
                        float ny1 = (1.f - uu.y) * ns.y + uu.y * yo.y;
                        float nl0 = (1.f - uu.x) * nd.x + uu.x * lo.x;
                        float nl1 = (1.f - uu.y) * nd.y + uu.y * lo.y;
                        *reinterpret_cast<u64*>(S->yT + XI(c, pr))  = pk2(ny0, ny1);
                        *reinterpret_cast<u64*>(S->lvT + XI(c, pr)) = pk2(nl0, nl1);
                    }
            }
            cb = nxt1(cb);
        }
    }

    CPWAIT0(); __syncthreads();

    // ===== output: yi (4096x64) then yi_logvar (4096x64) =====
    for (int i = tid; i < TM * DLAT; i += NTH) {
        int r = i >> 6, c = i & 63;
        int a = XI(c, r >> 1) + (r & 1);
        out[(size_t)(traj0 + r) * DLAT + c] = S->yT[a];
        out[(size_t)NT * DLAT + (size_t)(traj0 + r) * DLAT + c] = S->lvT[a];
    }
}

extern "C" void kernel_launch(void* const* d_in, const int* in_sizes, int n_in,
                              void* d_out, int out_size) {
    const float* data = (const float*)d_in[0];
    const float* ts   = (const float*)d_in[1];
    const float* Wo1  = (const float*)d_in[2];
    const float* bo1  = (const float*)d_in[3];
    const float* Wo2  = (const float*)d_in[4];
    const float* bo2  = (const float*)d_in[5];
    const float* Wu1  = (const float*)d_in[6];
    const float* bu1  = (const float*)d_in[7];
    const float* Wu2  = (const float*)d_in[8];
    const float* bu2  = (const float*)d_in[9];
    const float* Wr1  = (const float*)d_in[10];
    const float* br1  = (const float*)d_in[11];
    const float* Wr2  = (const float*)d_in[12];
    const float* br2  = (const float*)d_in[13];
    const float* Wn1  = (const float*)d_in[14];
    const float* bn1  = (const float*)d_in[15];
    const float* Wn2  = (const float*)d_in[16];
    const float* bn2  = (const float*)d_in[17];
    float* out = (float*)d_out;

    const int smem = (int)sizeof(Smem);
    cudaFuncSetAttribute(ode_rnn_kernel,
                         cudaFuncAttributeMaxDynamicSharedMemorySize, smem);
    ode_rnn_kernel<<<NT / TM, NTH, smem>>>(
        data, ts, Wo1, bo1, Wo2, bo2, Wu1, bu1, Wu2, bu2,
        Wr1, br1, Wr2, br2, Wn1, bn1, Wn2, bn2, out);
}